// round 9
// baseline (speedup 1.0000x reference)
#include <cuda_runtime.h>
#include <stdint.h>

// Gather: out[r, :] = table[idx[r], :]   rows=819200, D=64 f32 (256 B/row)
//
// Stage-and-burst structure:
//   - persistent blocks, each loops over 64-row tiles (16 KB of output)
//   - gather tile into SMEM (random 256B reads, LSU path, MLP-batched)
//   - emit tile as ONE cp.async.bulk shared->global copy (TMA bulk store:
//     16 KB contiguous DRAM write burst, no LSU stores)
//   - double-buffered so next tile's gather overlaps previous tile's store

#define LANES      16          // float4s per row
#define THREADS    256         // 16 groups of 16 lanes
#define TILE_ROWS  64          // rows per tile -> 16 KB
#define RPT        4           // rows per group (64 rows / 16 groups)
#define NBUF       2

__device__ __forceinline__ uint32_t smem_u32(const void* p) {
    return (uint32_t)__cvta_generic_to_shared(p);
}

__global__ __launch_bounds__(THREADS)
void gather_kernel(const int* __restrict__ indices,
                   const float4* __restrict__ table,
                   float4* __restrict__ out,
                   int num_rows)
{
    __shared__ __align__(128) float4 buf[NBUF][TILE_ROWS * LANES]; // 2 x 16 KB

    const int tid   = threadIdx.x;
    const int lane  = tid & 15;
    const int group = tid >> 4;            // 0..15

    const int num_tiles = num_rows / TILE_ROWS;

    int it = 0;
    for (int tile = blockIdx.x; tile < num_tiles; tile += gridDim.x, it++) {
        const int b = it & 1;

        // Make sure the bulk copy that last read buf[b] has finished reading.
        if (it >= NBUF) {
            if (tid == 0)
                asm volatile("cp.async.bulk.wait_group.read 1;" ::: "memory");
            __syncthreads();
        }

        const int rowBase = tile * TILE_ROWS + group * RPT;

        // 1) 4 indices as one int4 (rowBase % 4 == 0)
        int4 iv = __ldg((const int4*)(indices + rowBase));
        int idx[RPT] = { iv.x, iv.y, iv.z, iv.w };

        // 2) batched random table reads (L2-only; L1 useless for 143MB set)
        float4 v[RPT];
#pragma unroll
        for (int u = 0; u < RPT; u++)
            v[u] = __ldcg(&table[(size_t)idx[u] * LANES + lane]);

        // 3) stage into smem tile (conflict-free: contiguous 16B per lane)
#pragma unroll
        for (int u = 0; u < RPT; u++)
            buf[b][(group * RPT + u) * LANES + lane] = v[u];

        __syncthreads();

        // 4) one 16 KB bulk store, issued by a single thread
        if (tid == 0) {
            asm volatile("fence.proxy.async.shared::cta;" ::: "memory");
            const float4* gdst = out + (size_t)tile * TILE_ROWS * LANES;
            asm volatile(
                "cp.async.bulk.global.shared::cta.bulk_group [%0], [%1], %2;"
                :: "l"(gdst), "r"(smem_u32(&buf[b][0])),
                   "r"((uint32_t)(TILE_ROWS * LANES * sizeof(float4)))
                : "memory");
            asm volatile("cp.async.bulk.commit_group;" ::: "memory");
        }
    }

    // Tail rows (num_rows not multiple of TILE_ROWS): direct stores, block 0.
    if (blockIdx.x == 0) {
        for (int r = num_tiles * TILE_ROWS + (tid >> 4); r < num_rows;
             r += THREADS / LANES) {
            int idx = __ldg(&indices[r]);
            float4 v = __ldcg(&table[(size_t)idx * LANES + lane]);
            out[(size_t)r * LANES + lane] = v;
        }
    }

    // Drain all outstanding bulk stores before CTA exit.
    if (tid == 0)
        asm volatile("cp.async.bulk.wait_group 0;" ::: "memory");
}

extern "C" void kernel_launch(void* const* d_in, const int* in_sizes, int n_in,
                              void* d_out, int out_size)
{
    const int* indices  = (const int*)d_in[0];      // [B*F] int32
    const float4* table = (const float4*)d_in[1];   // [V, 64] f32 as float4
    float4* out = (float4*)d_out;

    int num_rows  = in_sizes[0];                    // 819200
    int num_tiles = num_rows / TILE_ROWS;           // 12800

    // Persistent grid: ~8 blocks/SM on 148 SMs, capped by tile count.
    int blocks = 148 * 8;
    if (blocks > num_tiles) blocks = num_tiles;
    if (blocks < 1) blocks = 1;

    gather_kernel<<<blocks, THREADS>>>(indices, table, out, num_rows);
}

// round 13
// speedup vs baseline: 1.1919x; 1.1919x over previous
#include <cuda_runtime.h>
#include <stdint.h>

// Gather: out[r, :] = table[idx[r], :]
// rows = 819200, D = 64 floats (256 B/row).
// 8 threads per row; each thread moves 32 B with a single 256-bit load.
// Each 8-thread group handles RPT=4 consecutive rows:
//   - 4 indices via one int4 broadcast load
//   - 4 independent ld.global.nc.L2::evict_last.v8.b32 (table lines pinned in L2)
//   - stores via st.global.cs (evict-first; write stream doesn't displace table)

#define THREADS 256
#define RPT 4               // rows per 8-thread group

struct V8 { uint32_t r[8]; };

__device__ __forceinline__ V8 ldg256_keep(const void* p) {
    V8 v;
    asm volatile(
        "ld.global.nc.L2::evict_last.v8.b32 {%0,%1,%2,%3,%4,%5,%6,%7}, [%8];"
        : "=r"(v.r[0]), "=r"(v.r[1]), "=r"(v.r[2]), "=r"(v.r[3]),
          "=r"(v.r[4]), "=r"(v.r[5]), "=r"(v.r[6]), "=r"(v.r[7])
        : "l"(p));
    return v;
}

__device__ __forceinline__ void stcs128(float4* p, const uint32_t* r) {
    asm volatile("st.global.cs.v4.b32 [%0], {%1,%2,%3,%4};"
                 :: "l"(p), "r"(r[0]), "r"(r[1]), "r"(r[2]), "r"(r[3])
                 : "memory");
}

__global__ __launch_bounds__(THREADS)
void gather_kernel(const int* __restrict__ indices,
                   const float* __restrict__ table,
                   float* __restrict__ out,
                   int num_rows)
{
    int t = blockIdx.x * blockDim.x + threadIdx.x;
    int lane = t & 7;                  // which 32B chunk within a row (0..7)
    int rowBase = (t >> 3) * RPT;      // first of RPT consecutive rows

    if (rowBase >= num_rows) return;

    if (rowBase + RPT <= num_rows) {
        // 1) 4 indices via one int4 broadcast
        int4 iv = __ldg((const int4*)(indices + rowBase));
        int idx[RPT] = { iv.x, iv.y, iv.z, iv.w };

        // 2) 4 independent 256-bit table loads, L2 evict_last
        V8 v[RPT];
#pragma unroll
        for (int u = 0; u < RPT; u++)
            v[u] = ldg256_keep(table + (size_t)idx[u] * 64 + lane * 8);

        // 3) streaming stores: 2x 128-bit per row-chunk
#pragma unroll
        for (int u = 0; u < RPT; u++) {
            float* dst = out + (size_t)(rowBase + u) * 64 + lane * 8;
            stcs128((float4*)dst,       &v[u].r[0]);
            stcs128((float4*)(dst + 4), &v[u].r[4]);
        }
    } else {
        // tail
        for (int u = 0; u < RPT; u++) {
            int r = rowBase + u;
            if (r >= num_rows) break;
            int idx = __ldg(&indices[r]);
            V8 v = ldg256_keep(table + (size_t)idx * 64 + lane * 8);
            float* dst = out + (size_t)r * 64 + lane * 8;
            stcs128((float4*)dst,       &v.r[0]);
            stcs128((float4*)(dst + 4), &v.r[4]);
        }
    }
}

extern "C" void kernel_launch(void* const* d_in, const int* in_sizes, int n_in,
                              void* d_out, int out_size)
{
    const int* indices = (const int*)d_in[0];    // [B*F] int32
    const float* table = (const float*)d_in[1];  // [V, 64] f32
    float* out = (float*)d_out;

    int num_rows = in_sizes[0];                  // 819200
    long long groups = ((long long)num_rows + RPT - 1) / RPT;  // 8-thread groups
    long long total_threads = groups * 8;
    int blocks = (int)((total_threads + THREADS - 1) / THREADS);

    gather_kernel<<<blocks, THREADS>>>(indices, table, out, num_rows);
}